// round 1
// baseline (speedup 1.0000x reference)
#include <cuda_runtime.h>
#include <cstdint>

#define NB 64
#define S  512   // P = H = 512
#define DD 512   // feature dim
#define NEG_MASK -999999.0f

// Scratch (allocation-free rule: __device__ globals)
__device__ float g_sim [ (size_t)NB * S * S ];
__device__ float g_attA[ (size_t)NB * S * S ];
__device__ float g_attB[ (size_t)NB * S * S ];

// ---------------------------------------------------------------------------
// Batched 512x512x512 fp32 GEMM, 128x128 tile, BK=16, 8x8 per thread.
// MODE 0 (NT): C[m,n] = sum_k A[m*512+k] * B[n*512+k]
// MODE 1 (NN): C[m,n] = sum_k A[m*512+k] * B[k*512+n]
// MODE 2 (TN): C[m,n] = sum_k A[k*512+m] * B[k*512+n]
// Grid: (4, 4, NB), Block: 256
// ---------------------------------------------------------------------------
template<int MODE>
__global__ __launch_bounds__(256)
void gemm512_kernel(const float* __restrict__ A,
                    const float* __restrict__ Bg,
                    float* __restrict__ C)
{
    const int b = blockIdx.z;
    A  += (size_t)b * S * S;
    Bg += (size_t)b * S * S;
    C  += (size_t)b * S * S;

    __shared__ float As[16][132];
    __shared__ float Bs[16][132];

    const int tid = threadIdx.x;
    const int tx  = tid & 15;      // n
    const int ty  = tid >> 4;      // m
    const int m0  = blockIdx.y * 128;
    const int n0  = blockIdx.x * 128;

    float acc[8][8];
#pragma unroll
    for (int i = 0; i < 8; i++)
#pragma unroll
        for (int j = 0; j < 8; j++) acc[i][j] = 0.0f;

    for (int k0 = 0; k0 < S; k0 += 16) {
        // ---- load A tile (128 rows m x 16 cols k) into As[k][m] ----
#pragma unroll
        for (int l = 0; l < 2; l++) {
            int idx = tid + l * 256;          // 0..511 float4 loads
            if (MODE == 2) {
                // A is [K, M]: rows k0..k0+15, cols m0..m0+127
                int r = idx >> 5, c4 = idx & 31;
                float4 v = *(const float4*)&A[(k0 + r) * S + m0 + c4 * 4];
                As[r][c4 * 4 + 0] = v.x; As[r][c4 * 4 + 1] = v.y;
                As[r][c4 * 4 + 2] = v.z; As[r][c4 * 4 + 3] = v.w;
            } else {
                // A is [M, K]: rows m0..m0+127, cols k0..k0+15
                int r = idx >> 2, c4 = idx & 3;
                float4 v = *(const float4*)&A[(m0 + r) * S + k0 + c4 * 4];
                As[c4 * 4 + 0][r] = v.x; As[c4 * 4 + 1][r] = v.y;
                As[c4 * 4 + 2][r] = v.z; As[c4 * 4 + 3][r] = v.w;
            }
        }
        // ---- load B tile (16 k x 128 n) into Bs[k][n] ----
#pragma unroll
        for (int l = 0; l < 2; l++) {
            int idx = tid + l * 256;
            if (MODE == 0) {
                // B is [N, K]: rows n0..n0+127, cols k0..k0+15
                int r = idx >> 2, c4 = idx & 3;
                float4 v = *(const float4*)&Bg[(n0 + r) * S + k0 + c4 * 4];
                Bs[c4 * 4 + 0][r] = v.x; Bs[c4 * 4 + 1][r] = v.y;
                Bs[c4 * 4 + 2][r] = v.z; Bs[c4 * 4 + 3][r] = v.w;
            } else {
                // B is [K, N]: rows k0..k0+15, cols n0..n0+127
                int r = idx >> 5, c4 = idx & 31;
                float4 v = *(const float4*)&Bg[(k0 + r) * S + n0 + c4 * 4];
                Bs[r][c4 * 4 + 0] = v.x; Bs[r][c4 * 4 + 1] = v.y;
                Bs[r][c4 * 4 + 2] = v.z; Bs[r][c4 * 4 + 3] = v.w;
            }
        }
        __syncthreads();

#pragma unroll
        for (int k = 0; k < 16; k++) {
            float4 a0 = *(const float4*)&As[k][ty * 8];
            float4 a1 = *(const float4*)&As[k][ty * 8 + 4];
            float4 b0 = *(const float4*)&Bs[k][tx * 8];
            float4 b1 = *(const float4*)&Bs[k][tx * 8 + 4];
            float a[8] = {a0.x, a0.y, a0.z, a0.w, a1.x, a1.y, a1.z, a1.w};
            float bb[8] = {b0.x, b0.y, b0.z, b0.w, b1.x, b1.y, b1.z, b1.w};
#pragma unroll
            for (int i = 0; i < 8; i++)
#pragma unroll
                for (int j = 0; j < 8; j++)
                    acc[i][j] = fmaf(a[i], bb[j], acc[i][j]);
        }
        __syncthreads();
    }

#pragma unroll
    for (int i = 0; i < 8; i++) {
        float* crow = &C[(m0 + ty * 8 + i) * S + n0 + tx * 8];
        *(float4*)&crow[0] = make_float4(acc[i][0], acc[i][1], acc[i][2], acc[i][3]);
        *(float4*)&crow[4] = make_float4(acc[i][4], acc[i][5], acc[i][6], acc[i][7]);
    }
}

// ---------------------------------------------------------------------------
// Row softmax (attention_a): softmax over h of sim[b,p,:] + NEG*(pre_mask==0)
// Grid: (S, NB), Block: 256 (2 elems/thread)
// ---------------------------------------------------------------------------
__global__ __launch_bounds__(256)
void softmax_row_kernel(const int* __restrict__ pre_mask)
{
    const int b = blockIdx.y, p = blockIdx.x, t = threadIdx.x;
    const float c = (pre_mask[b * S + p] == 0) ? NEG_MASK : 0.0f;
    const float* row = g_sim + ((size_t)b * S + p) * S;

    float v0 = row[t] + c;
    float v1 = row[t + 256] + c;

    __shared__ float red[256];
    red[t] = fmaxf(v0, v1);
    __syncthreads();
#pragma unroll
    for (int o = 128; o > 0; o >>= 1) {
        if (t < o) red[t] = fmaxf(red[t], red[t + o]);
        __syncthreads();
    }
    const float M = red[0];
    __syncthreads();

    float e0 = __expf(v0 - M);
    float e1 = __expf(v1 - M);
    red[t] = e0 + e1;
    __syncthreads();
#pragma unroll
    for (int o = 128; o > 0; o >>= 1) {
        if (t < o) red[t] += red[t + o];
        __syncthreads();
    }
    const float inv = 1.0f / red[0];

    float* arow = g_attA + ((size_t)b * S + p) * S;
    arow[t]       = e0 * inv;
    arow[t + 256] = e1 * inv;
}

// ---------------------------------------------------------------------------
// Column softmax (attention_b): softmax over p of sim[b,:,h] + NEG*(hyp_mask==0)
// Grid: (S/64, NB), Block: 256 = 64 columns x 4 p-strips of 128
// ---------------------------------------------------------------------------
__global__ __launch_bounds__(256)
void softmax_col_kernel(const int* __restrict__ hyp_mask)
{
    const int b     = blockIdx.y;
    const int col   = threadIdx.x & 63;
    const int strip = threadIdx.x >> 6;           // 0..3
    const int h     = blockIdx.x * 64 + col;
    const float c   = (hyp_mask[b * S + h] == 0) ? NEG_MASK : 0.0f;
    const float* simb = g_sim + (size_t)b * S * S;

    // online max/sum over this strip's 128 rows
    float m = -3.0e38f, s = 0.0f;
    const int p0 = strip * 128;
    for (int p = p0; p < p0 + 128; ++p) {
        float v = simb[p * S + h] + c;
        if (v > m) { s = s * __expf(m - v) + 1.0f; m = v; }
        else       { s += __expf(v - m); }
    }

    __shared__ float sm[4][64], ss[4][64];
    sm[strip][col] = m;
    ss[strip][col] = s;
    __syncthreads();

    float M = -3.0e38f;
#pragma unroll
    for (int i = 0; i < 4; i++) M = fmaxf(M, sm[i][col]);
    float Ssum = 0.0f;
#pragma unroll
    for (int i = 0; i < 4; i++) Ssum += ss[i][col] * __expf(sm[i][col] - M);
    const float inv = 1.0f / Ssum;

    float* attb = g_attB + (size_t)b * S * S;
    for (int p = p0; p < p0 + 128; ++p) {
        float v = simb[p * S + h] + c;
        attb[p * S + h] = __expf(v - M) * inv;
    }
}

// ---------------------------------------------------------------------------
extern "C" void kernel_launch(void* const* d_in, const int* in_sizes, int n_in,
                              void* d_out, int out_size)
{
    const float* premise  = (const float*)d_in[0];
    const int*   pre_mask = (const int*)  d_in[1];
    const float* hypo     = (const float*)d_in[2];
    const int*   hyp_mask = (const int*)  d_in[3];
    float* out1 = (float*)d_out;                        // attended_premises
    float* out2 = out1 + (size_t)NB * S * S;            // attended_hypothesis

    float *sim, *attA, *attB;
    cudaGetSymbolAddress((void**)&sim,  g_sim);
    cudaGetSymbolAddress((void**)&attA, g_attA);
    cudaGetSymbolAddress((void**)&attB, g_attB);

    dim3 gblk(256);
    dim3 ggrid(S / 128, S / 128, NB);

    // 1. sim = premise @ hypothesis^T   (NT)
    gemm512_kernel<0><<<ggrid, gblk>>>(premise, hypo, sim);

    // 2. attention_a = softmax_rows(sim + NEG*pre_pad)
    softmax_row_kernel<<<dim3(S, NB), 256>>>(pre_mask);

    // 3. attention_b = softmax_cols(sim + NEG*hyp_pad)
    softmax_col_kernel<<<dim3(S / 64, NB), 256>>>(hyp_mask);

    // 4. attended_premises = attA @ hypothesis   (NN)
    gemm512_kernel<1><<<ggrid, gblk>>>(attA, hypo, out1);

    // 5. attended_hypothesis = attB^T @ premise  (TN)
    gemm512_kernel<2><<<ggrid, gblk>>>(attB, premise, out2);
}

// round 3
// speedup vs baseline: 1.6151x; 1.6151x over previous
#include <cuda_runtime.h>
#include <cuda_fp16.h>
#include <cstdint>

#define NB 64
#define S  512
#define NEG_MASK -999999.0f

#define TENS ((size_t)NB * S * S)   // 16,777,216 elements per tensor

// ---------------- scratch (__device__ globals: allocation-free rule) -------
__device__ float  g_sim[TENS];                // fp32 similarity
__device__ __half g_buf[12 * TENS];           // 12 fp16 tensors (hi/lo splits)

// slot indices into g_buf
#define PRE_HI  0
#define PRE_LO  1
#define PRE_THI 2
#define PRE_TLO 3
#define HYP_HI  4
#define HYP_LO  5
#define HYP_THI 6
#define HYP_TLO 7
#define ATT_AHI 8
#define ATT_ALO 9
#define ATT_BHI 10
#define ATT_BLO 11

// ---------------- helpers --------------------------------------------------
__device__ __forceinline__ uint32_t smem_to_u32(const void* p) {
    uint32_t a;
    asm("{ .reg .u64 t; cvta.to.shared.u64 t, %1; cvt.u32.u64 %0, t; }" : "=r"(a) : "l"(p));
    return a;
}

__device__ __forceinline__ void ldsm_x4(uint32_t* r, uint32_t addr) {
    asm volatile("ldmatrix.sync.aligned.m8n8.x4.shared.b16 {%0,%1,%2,%3}, [%4];"
                 : "=r"(r[0]), "=r"(r[1]), "=r"(r[2]), "=r"(r[3]) : "r"(addr));
}
__device__ __forceinline__ void ldsm_x2(uint32_t* r, uint32_t addr) {
    asm volatile("ldmatrix.sync.aligned.m8n8.x2.shared.b16 {%0,%1}, [%2];"
                 : "=r"(r[0]), "=r"(r[1]) : "r"(addr));
}
__device__ __forceinline__ void mma16816(float* c, const uint32_t* a, const uint32_t* b) {
    asm volatile(
        "mma.sync.aligned.m16n8k16.row.col.f32.f16.f16.f32 "
        "{%0,%1,%2,%3}, {%4,%5,%6,%7}, {%8,%9}, {%0,%1,%2,%3};"
        : "+f"(c[0]), "+f"(c[1]), "+f"(c[2]), "+f"(c[3])
        : "r"(a[0]), "r"(a[1]), "r"(a[2]), "r"(a[3]), "r"(b[0]), "r"(b[1]));
}

// ---------------------------------------------------------------------------
// Conversion: fp32 X [B,512,512] -> hi/lo fp16 row-major + hi/lo transposed
// grid (16,16,NB), block (32,8)
// ---------------------------------------------------------------------------
__global__ __launch_bounds__(256)
void convert_split_kernel(const float* __restrict__ X,
                          __half* __restrict__ hi, __half* __restrict__ lo,
                          __half* __restrict__ thi, __half* __restrict__ tlo)
{
    __shared__ __half sh[32][33], sl[32][33];
    const int tx = threadIdx.x, ty = threadIdx.y;
    const size_t base = (size_t)blockIdx.z * S * S;
    const int r0 = blockIdx.y * 32, c0 = blockIdx.x * 32;
#pragma unroll
    for (int j = 0; j < 4; j++) {
        int rl = ty + j * 8;
        size_t idx = base + (size_t)(r0 + rl) * S + c0 + tx;
        float x = X[idx];
        __half h = __float2half_rn(x);
        __half l = __float2half_rn(x - __half2float(h));
        hi[idx] = h;
        lo[idx] = l;
        sh[rl][tx] = h;
        sl[rl][tx] = l;
    }
    __syncthreads();
#pragma unroll
    for (int j = 0; j < 4; j++) {
        int cl = ty + j * 8;
        size_t idx = base + (size_t)(c0 + cl) * S + r0 + tx;
        thi[idx] = sh[tx][cl];
        tlo[idx] = sl[tx][cl];
    }
}

// ---------------------------------------------------------------------------
// fp16-split tensor-core GEMM via mma.sync:
//   C[m,n] = sum_k (Ahi+Alo)[m,k] * (Bhi+Blo)[n,k]      (lo*lo dropped)
// A,B row-major [512,512] per batch, K contiguous. C fp32 row-major.
// grid (4,4,NB), 256 threads, 3-stage cp.async pipeline, 192 KB dynamic smem.
// Stage layout: Ahi | Alo | Bhi | Blo, each 128 rows x 64 halves (128 B/row),
// 16 KB per tile, SW128 chunk-XOR swizzle (chunk' = chunk ^ (row & 7)).
// ---------------------------------------------------------------------------
#define GEMM_SMEM (3 * 65536)

__global__ __launch_bounds__(256)
void gemm_tc_kernel(const __half* __restrict__ Ahi, const __half* __restrict__ Alo,
                    const __half* __restrict__ Bhi, const __half* __restrict__ Blo,
                    float* __restrict__ C)
{
    extern __shared__ char smem[];
    const uint32_t sb = smem_to_u32(smem);
    const int tid = threadIdx.x;
    const int lane = tid & 31, wid = tid >> 5;
    const int wm = wid >> 2;            // 0..1  (m direction, 64 rows each)
    const int wn = wid & 3;             // 0..3  (n direction, 32 cols each)
    const size_t boff = (size_t)blockIdx.z * S * S;
    const int m0 = blockIdx.y * 128, n0 = blockIdx.x * 128;

    const __half* gsrc[4] = {
        Ahi + boff + (size_t)m0 * S,
        Alo + boff + (size_t)m0 * S,
        Bhi + boff + (size_t)n0 * S,
        Blo + boff + (size_t)n0 * S
    };

    auto load_stage = [&](int st, int k0) {
        uint32_t base = sb + st * 65536;
#pragma unroll
        for (int t = 0; t < 4; t++) {
            const __half* g = gsrc[t] + k0;
            uint32_t tb = base + t * 16384;
#pragma unroll
            for (int j = 0; j < 4; j++) {
                int idx = j * 256 + tid;           // 0..1023 16B chunks
                int row = idx >> 3, c = idx & 7;
                uint32_t dst = tb + row * 128 + ((uint32_t)(c ^ (row & 7)) << 4);
                const void* src = g + row * S + c * 8;
                asm volatile("cp.async.cg.shared.global [%0], [%1], 16;"
                             :: "r"(dst), "l"(src) : "memory");
            }
        }
    };

    float acc[4][4][4];
#pragma unroll
    for (int i = 0; i < 4; i++)
#pragma unroll
        for (int j = 0; j < 4; j++)
#pragma unroll
            for (int q = 0; q < 4; q++) acc[i][j][q] = 0.0f;

    load_stage(0, 0);
    asm volatile("cp.async.commit_group;" ::: "memory");
    load_stage(1, 64);
    asm volatile("cp.async.commit_group;" ::: "memory");

    for (int i = 0; i < 8; i++) {
        __syncthreads();                       // everyone done reading stage (i-1)%3
        if (i + 2 < 8) load_stage((i + 2) % 3, (i + 2) * 64);
        asm volatile("cp.async.commit_group;" ::: "memory");   // group per iter (maybe empty)
        asm volatile("cp.async.wait_group 2;" ::: "memory");   // stage i's group done
        __syncthreads();

        const uint32_t stb = sb + (i % 3) * 65536;
#pragma unroll
        for (int ks = 0; ks < 4; ks++) {       // 4 x k16 within the k64 chunk
            uint32_t ah[4][4], al[4][4], bh[4][2], bl[4][2];
#pragma unroll
            for (int mf = 0; mf < 4; mf++) {
                int row = wm * 64 + mf * 16 + (lane & 15);
                int ch = (ks * 2 + (lane >> 4)) ^ (row & 7);
                uint32_t off = row * 128 + (ch << 4);
                ldsm_x4(ah[mf], stb + off);
                ldsm_x4(al[mf], stb + 16384 + off);
            }
#pragma unroll
            for (int nf = 0; nf < 4; nf++) {
                int row = wn * 32 + nf * 8 + (lane & 7);
                int ch = (ks * 2 + ((lane >> 3) & 1)) ^ (row & 7);
                uint32_t off = row * 128 + (ch << 4);
                ldsm_x2(bh[nf], stb + 32768 + off);
                ldsm_x2(bl[nf], stb + 49152 + off);
            }
#pragma unroll
            for (int mf = 0; mf < 4; mf++)
#pragma unroll
                for (int nf = 0; nf < 4; nf++) {
                    mma16816(acc[mf][nf], ah[mf], bh[nf]);
                    mma16816(acc[mf][nf], ah[mf], bl[nf]);
                    mma16816(acc[mf][nf], al[mf], bh[nf]);
                }
        }
    }

    // epilogue: c frag (m16n8): {c0,c1}=(r, c..c+1), {c2,c3}=(r+8, c..c+1)
    float* Cb = C + boff;
#pragma unroll
    for (int mf = 0; mf < 4; mf++) {
#pragma unroll
        for (int nf = 0; nf < 4; nf++) {
            int r  = m0 + wm * 64 + mf * 16 + (lane >> 2);
            int cc = n0 + wn * 32 + nf * 8 + (lane & 3) * 2;
            *(float2*)&Cb[(size_t)r * S + cc]       = make_float2(acc[mf][nf][0], acc[mf][nf][1]);
            *(float2*)&Cb[(size_t)(r + 8) * S + cc] = make_float2(acc[mf][nf][2], acc[mf][nf][3]);
        }
    }
}

// ---------------------------------------------------------------------------
// Row softmax (attention_a) -> hi/lo fp16, row-major [p][h]. grid (S,NB), 256
// ---------------------------------------------------------------------------
__global__ __launch_bounds__(256)
void softmax_row_kernel(const int* __restrict__ pre_mask,
                        __half* __restrict__ ahi, __half* __restrict__ alo)
{
    const int b = blockIdx.y, p = blockIdx.x, t = threadIdx.x;
    const float c = (pre_mask[b * S + p] == 0) ? NEG_MASK : 0.0f;
    const float* row = g_sim + ((size_t)b * S + p) * S;

    float v0 = row[t] + c;
    float v1 = row[t + 256] + c;

    __shared__ float red[256];
    red[t] = fmaxf(v0, v1);
    __syncthreads();
#pragma unroll
    for (int o = 128; o > 0; o >>= 1) {
        if (t < o) red[t] = fmaxf(red[t], red[t + o]);
        __syncthreads();
    }
    const float M = red[0];
    __syncthreads();

    float e0 = __expf(v0 - M);
    float e1 = __expf(v1 - M);
    red[t] = e0 + e1;
    __syncthreads();
#pragma unroll
    for (int o = 128; o > 0; o >>= 1) {
        if (t < o) red[t] += red[t + o];
        __syncthreads();
    }
    const float inv = 1.0f / red[0];

    const size_t off = ((size_t)b * S + p) * S;
    float w0 = e0 * inv, w1 = e1 * inv;
    __half h0 = __float2half_rn(w0);
    __half h1 = __float2half_rn(w1);
    ahi[off + t]       = h0;
    alo[off + t]       = __float2half_rn(w0 - __half2float(h0));
    ahi[off + t + 256] = h1;
    alo[off + t + 256] = __float2half_rn(w1 - __half2float(h1));
}

// ---------------------------------------------------------------------------
// Column softmax (attention_b) -> hi/lo fp16 written TRANSPOSED: [h][p].
// grid (S/64, NB), block 256 = 64 cols x 4 p-strips
// ---------------------------------------------------------------------------
__global__ __launch_bounds__(256)
void softmax_col_kernel(const int* __restrict__ hyp_mask,
                        __half* __restrict__ bhi, __half* __restrict__ blo)
{
    const int b     = blockIdx.y;
    const int col   = threadIdx.x & 63;
    const int strip = threadIdx.x >> 6;
    const int h     = blockIdx.x * 64 + col;
    const float c   = (hyp_mask[b * S + h] == 0) ? NEG_MASK : 0.0f;
    const float* simb = g_sim + (size_t)b * S * S;

    float m = -3.0e38f, s = 0.0f;
    const int p0 = strip * 128;
    for (int p = p0; p < p0 + 128; ++p) {
        float v = simb[p * S + h] + c;
        if (v > m) { s = s * __expf(m - v) + 1.0f; m = v; }
        else       { s += __expf(v - m); }
    }

    __shared__ float sm[4][64], ss[4][64];
    sm[strip][col] = m;
    ss[strip][col] = s;
    __syncthreads();

    float M = -3.0e38f;
#pragma unroll
    for (int i = 0; i < 4; i++) M = fmaxf(M, sm[i][col]);
    float Ssum = 0.0f;
#pragma unroll
    for (int i = 0; i < 4; i++) Ssum += ss[i][col] * __expf(sm[i][col] - M);
    const float inv = 1.0f / Ssum;

    const size_t ob = (size_t)b * S * S + (size_t)h * S;
    for (int p = p0; p < p0 + 128; ++p) {
        float v = simb[p * S + h] + c;
        float w = __expf(v - M) * inv;
        __half hh = __float2half_rn(w);
        bhi[ob + p] = hh;
        blo[ob + p] = __float2half_rn(w - __half2float(hh));
    }
}

// ---------------------------------------------------------------------------
extern "C" void kernel_launch(void* const* d_in, const int* in_sizes, int n_in,
                              void* d_out, int out_size)
{
    const float* premise  = (const float*)d_in[0];
    const int*   pre_mask = (const int*)  d_in[1];
    const float* hypo     = (const float*)d_in[2];
    const int*   hyp_mask = (const int*)  d_in[3];
    float* out1 = (float*)d_out;                 // attended_premises
    float* out2 = out1 + TENS;                   // attended_hypothesis

    float*  sim;
    __half* buf;
    cudaGetSymbolAddress((void**)&sim, g_sim);
    cudaGetSymbolAddress((void**)&buf, g_buf);
    auto slot = [&](int i) { return buf + (size_t)i * TENS; };

    cudaFuncSetAttribute(gemm_tc_kernel,
                         cudaFuncAttributeMaxDynamicSharedMemorySize, GEMM_SMEM);

    dim3 cgrid(16, 16, NB), cblk(32, 8);
    dim3 ggrid(4, 4, NB);

    // 1. hi/lo fp16 splits (+transposes) of inputs
    convert_split_kernel<<<cgrid, cblk>>>(premise, slot(PRE_HI), slot(PRE_LO),
                                          slot(PRE_THI), slot(PRE_TLO));
    convert_split_kernel<<<cgrid, cblk>>>(hypo, slot(HYP_HI), slot(HYP_LO),
                                          slot(HYP_THI), slot(HYP_TLO));

    // 2. sim = premise @ hypothesis^T   (A=[p][d], B=[h][d], K=d)
    gemm_tc_kernel<<<ggrid, 256, GEMM_SMEM>>>(slot(PRE_HI), slot(PRE_LO),
                                              slot(HYP_HI), slot(HYP_LO), sim);

    // 3. softmaxes -> fp16 hi/lo attention (attB emitted transposed)
    softmax_row_kernel<<<dim3(S, NB), 256>>>(pre_mask, slot(ATT_AHI), slot(ATT_ALO));
    softmax_col_kernel<<<dim3(S / 64, NB), 256>>>(hyp_mask, slot(ATT_BHI), slot(ATT_BLO));

    // 4. attended_premises = attA @ hyp    (A=attA [p][h], B=hypT [d][h], K=h)
    gemm_tc_kernel<<<ggrid, 256, GEMM_SMEM>>>(slot(ATT_AHI), slot(ATT_ALO),
                                              slot(HYP_THI), slot(HYP_TLO), out1);

    // 5. attended_hypothesis = attB^T @ pre (A=attBT [h][p], B=preT [d][p], K=p)
    gemm_tc_kernel<<<ggrid, 256, GEMM_SMEM>>>(slot(ATT_BHI), slot(ATT_BLO),
                                              slot(PRE_THI), slot(PRE_TLO), out2);
}

// round 4
// speedup vs baseline: 3.0995x; 1.9190x over previous
#include <cuda_runtime.h>
#include <cuda_fp16.h>
#include <cstdint>

#define NB 64
#define S  512
#define NEG_MASK -999999.0f

#define TENS ((size_t)NB * S * S)

// ---------------- scratch ---------------------------------------------------
__device__ float  g_sim[TENS];
__device__ __half g_buf[10 * TENS];

#define PRE_HI  0
#define PRE_LO  1
#define PRE_THI 2
#define HYP_HI  3
#define HYP_LO  4
#define HYP_THI 5
#define ATT_AHI 6
#define ATT_ALO 7
#define ATT_BHI 8
#define ATT_BLO 9

// ---------------- helpers ---------------------------------------------------
__device__ __forceinline__ uint32_t smem_to_u32(const void* p) {
    uint32_t a;
    asm("{ .reg .u64 t; cvta.to.shared.u64 t, %1; cvt.u32.u64 %0, t; }" : "=r"(a) : "l"(p));
    return a;
}
__device__ __forceinline__ void ldsm_x4(uint32_t* r, uint32_t addr) {
    asm volatile("ldmatrix.sync.aligned.m8n8.x4.shared.b16 {%0,%1,%2,%3}, [%4];"
                 : "=r"(r[0]), "=r"(r[1]), "=r"(r[2]), "=r"(r[3]) : "r"(addr));
}
__device__ __forceinline__ void ldsm_x2(uint32_t* r, uint32_t addr) {
    asm volatile("ldmatrix.sync.aligned.m8n8.x2.shared.b16 {%0,%1}, [%2];"
                 : "=r"(r[0]), "=r"(r[1]) : "r"(addr));
}
__device__ __forceinline__ void mma16816(float* c, const uint32_t* a, const uint32_t* b) {
    asm volatile(
        "mma.sync.aligned.m16n8k16.row.col.f32.f16.f16.f32 "
        "{%0,%1,%2,%3}, {%4,%5,%6,%7}, {%8,%9}, {%0,%1,%2,%3};"
        : "+f"(c[0]), "+f"(c[1]), "+f"(c[2]), "+f"(c[3])
        : "r"(a[0]), "r"(a[1]), "r"(a[2]), "r"(a[3]), "r"(b[0]), "r"(b[1]));
}

// ---------------------------------------------------------------------------
// Conversion: fp32 X -> hi/lo fp16 row-major + hi fp16 transposed
// grid (16,16,NB), block (32,8)
// ---------------------------------------------------------------------------
__global__ __launch_bounds__(256)
void convert_split_kernel(const float* __restrict__ X,
                          __half* __restrict__ hi, __half* __restrict__ lo,
                          __half* __restrict__ thi)
{
    __shared__ __half sh[32][33];
    const int tx = threadIdx.x, ty = threadIdx.y;
    const size_t base = (size_t)blockIdx.z * S * S;
    const int r0 = blockIdx.y * 32, c0 = blockIdx.x * 32;
#pragma unroll
    for (int j = 0; j < 4; j++) {
        int rl = ty + j * 8;
        size_t idx = base + (size_t)(r0 + rl) * S + c0 + tx;
        float x = X[idx];
        __half h = __float2half_rn(x);
        hi[idx] = h;
        lo[idx] = __float2half_rn(x - __half2float(h));
        sh[rl][tx] = h;
    }
    __syncthreads();
#pragma unroll
    for (int j = 0; j < 4; j++) {
        int cl = ty + j * 8;
        thi[base + (size_t)(c0 + cl) * S + r0 + tx] = sh[tx][cl];
    }
}

// ---------------------------------------------------------------------------
// fp16-split tensor-core GEMM (mma.sync m16n8k16), K-major A and B.
// NTERMS=3: C = Ahi*Bhi + Ahi*Blo + Alo*Bhi   (sim GEMM)
// NTERMS=2: C = Ahi*Bhi + Alo*Bhi             (attended GEMMs, B=values hi)
// 128x128 CTA tile, BK=32, 3-stage cp.async, 2 CTAs/SM.
// Stage tiles (8KB each, 128 rows x 32 halves, 64B rows, chunk-XOR swizzle):
//   Ahi | Alo | Bhi | [Blo]
// ---------------------------------------------------------------------------
template<int NTERMS>
__global__ __launch_bounds__(256, 2)
void gemm_tc_kernel(const __half* __restrict__ Ahi, const __half* __restrict__ Alo,
                    const __half* __restrict__ Bhi, const __half* __restrict__ Blo,
                    float* __restrict__ C)
{
    constexpr int NTILES  = NTERMS + 1;      // tiles per stage
    constexpr int TSZ     = 8192;            // bytes per tile
    constexpr int STSZ    = NTILES * TSZ;    // bytes per stage
    extern __shared__ char smem[];
    const uint32_t sb = smem_to_u32(smem);
    const int tid = threadIdx.x;
    const int lane = tid & 31, wid = tid >> 5;
    const int wm = wid >> 2;            // 0..1
    const int wn = wid & 3;             // 0..3
    const size_t boff = (size_t)blockIdx.z * S * S;
    const int m0 = blockIdx.y * 128, n0 = blockIdx.x * 128;

    const __half* gsrc[4] = {
        Ahi + boff + (size_t)m0 * S,
        Alo + boff + (size_t)m0 * S,
        Bhi + boff + (size_t)n0 * S,
        (NTERMS == 3 ? Blo + boff + (size_t)n0 * S : Bhi + boff + (size_t)n0 * S)
    };

    auto load_stage = [&](int st, int k0) {
        uint32_t base = sb + st * STSZ;
#pragma unroll
        for (int t = 0; t < NTILES; t++) {
            const __half* g = gsrc[t] + k0;
            uint32_t tb = base + t * TSZ;
#pragma unroll
            for (int j = 0; j < 2; j++) {
                int idx = j * 256 + tid;                 // 0..511 16B chunks
                int row = idx >> 2, c = idx & 3;
                uint32_t dst = tb + row * 64 + ((uint32_t)(c ^ ((row >> 1) & 3)) << 4);
                const void* src = g + row * S + c * 8;
                asm volatile("cp.async.cg.shared.global [%0], [%1], 16;"
                             :: "r"(dst), "l"(src) : "memory");
            }
        }
        asm volatile("cp.async.commit_group;" ::: "memory");
    };

    float acc[4][4][4];
#pragma unroll
    for (int i = 0; i < 4; i++)
#pragma unroll
        for (int j = 0; j < 4; j++)
#pragma unroll
            for (int q = 0; q < 4; q++) acc[i][j][q] = 0.0f;

    load_stage(0, 0);
    load_stage(1, 32);

    for (int i = 0; i < 16; i++) {
        __syncthreads();                       // prev-iter reads of stage (i+2)%3 done
        if (i + 2 < 16) load_stage((i + 2) % 3, (i + 2) * 32);
        else asm volatile("cp.async.commit_group;" ::: "memory");
        asm volatile("cp.async.wait_group 2;" ::: "memory");   // stage i landed
        __syncthreads();

        const uint32_t stb = sb + (i % 3) * STSZ;
#pragma unroll
        for (int ks = 0; ks < 2; ks++) {
            uint32_t ah[4][4], al[4][4];
#pragma unroll
            for (int mf = 0; mf < 4; mf++) {
                int row = wm * 64 + mf * 16 + (lane & 15);
                int ch = (ks * 2 + (lane >> 4)) ^ ((row >> 1) & 3);
                uint32_t off = row * 64 + (ch << 4);
                ldsm_x4(ah[mf], stb + off);
                ldsm_x4(al[mf], stb + TSZ + off);
            }
#pragma unroll
            for (int nf = 0; nf < 4; nf++) {
                int row = wn * 32 + nf * 8 + (lane & 7);
                int ch = (ks * 2 + ((lane >> 3) & 1)) ^ ((row >> 1) & 3);
                uint32_t off = row * 64 + (ch << 4);
                uint32_t bh[2], bl[2];
                ldsm_x2(bh, stb + 2 * TSZ + off);
                if (NTERMS == 3) ldsm_x2(bl, stb + 3 * TSZ + off);
#pragma unroll
                for (int mf = 0; mf < 4; mf++) {
                    mma16816(acc[mf][nf], ah[mf], bh);
                    if (NTERMS == 3) mma16816(acc[mf][nf], ah[mf], bl);
                    mma16816(acc[mf][nf], al[mf], bh);
                }
            }
        }
    }

    float* Cb = C + boff;
#pragma unroll
    for (int mf = 0; mf < 4; mf++) {
#pragma unroll
        for (int nf = 0; nf < 4; nf++) {
            int r  = m0 + wm * 64 + mf * 16 + (lane >> 2);
            int cc = n0 + wn * 32 + nf * 8 + (lane & 3) * 2;
            *(float2*)&Cb[(size_t)r * S + cc]       = make_float2(acc[mf][nf][0], acc[mf][nf][1]);
            *(float2*)&Cb[(size_t)(r + 8) * S + cc] = make_float2(acc[mf][nf][2], acc[mf][nf][3]);
        }
    }
}

// ---------------------------------------------------------------------------
// Row softmax (attention_a): one warp per row, shfl reductions, no bar.sync.
// grid (S/8, NB), block 256
// ---------------------------------------------------------------------------
__global__ __launch_bounds__(256)
void softmax_row_kernel(const int* __restrict__ pre_mask,
                        __half* __restrict__ ahi, __half* __restrict__ alo)
{
    const int b = blockIdx.y;
    const int w = threadIdx.x >> 5, lane = threadIdx.x & 31;
    const int p = blockIdx.x * 8 + w;
    const float c = (pre_mask[b * S + p] == 0) ? NEG_MASK : 0.0f;
    const size_t off = ((size_t)b * S + p) * S;
    const float* row = g_sim + off;

    float4 v[4];
#pragma unroll
    for (int seg = 0; seg < 4; seg++) {
        v[seg] = *(const float4*)&row[seg * 128 + lane * 4];
        v[seg].x += c; v[seg].y += c; v[seg].z += c; v[seg].w += c;
    }

    float M = -3.0e38f;
#pragma unroll
    for (int seg = 0; seg < 4; seg++)
        M = fmaxf(M, fmaxf(fmaxf(v[seg].x, v[seg].y), fmaxf(v[seg].z, v[seg].w)));
#pragma unroll
    for (int o = 16; o > 0; o >>= 1)
        M = fmaxf(M, __shfl_xor_sync(0xFFFFFFFFu, M, o));

    float s = 0.0f;
    float4 e[4];
#pragma unroll
    for (int seg = 0; seg < 4; seg++) {
        e[seg].x = __expf(v[seg].x - M); e[seg].y = __expf(v[seg].y - M);
        e[seg].z = __expf(v[seg].z - M); e[seg].w = __expf(v[seg].w - M);
        s += e[seg].x + e[seg].y + e[seg].z + e[seg].w;
    }
#pragma unroll
    for (int o = 16; o > 0; o >>= 1)
        s += __shfl_xor_sync(0xFFFFFFFFu, s, o);
    const float inv = 1.0f / s;

#pragma unroll
    for (int seg = 0; seg < 4; seg++) {
        float wv[4] = {e[seg].x * inv, e[seg].y * inv, e[seg].z * inv, e[seg].w * inv};
        __half hh[4], ll[4];
#pragma unroll
        for (int q = 0; q < 4; q++) {
            hh[q] = __float2half_rn(wv[q]);
            ll[q] = __float2half_rn(wv[q] - __half2float(hh[q]));
        }
        size_t o4 = off + seg * 128 + lane * 4;
        *(__half2*)&ahi[o4]     = __halves2half2(hh[0], hh[1]);
        *(__half2*)&ahi[o4 + 2] = __halves2half2(hh[2], hh[3]);
        *(__half2*)&alo[o4]     = __halves2half2(ll[0], ll[1]);
        *(__half2*)&alo[o4 + 2] = __halves2half2(ll[2], ll[3]);
    }
}

// ---------------------------------------------------------------------------
// Column softmax (attention_b) -> hi/lo fp16 written TRANSPOSED [h][p],
// coalesced via 64x64 smem transpose tiles. grid (S/64, NB), block 256.
// ---------------------------------------------------------------------------
__global__ __launch_bounds__(256)
void softmax_col_kernel(const int* __restrict__ hyp_mask,
                        __half* __restrict__ bhi, __half* __restrict__ blo)
{
    const int b   = blockIdx.y;
    const int h0  = blockIdx.x * 64;
    const int t   = threadIdx.x;
    const int col = t & 63, strip = t >> 6;
    const int h   = h0 + col;
    const float c = (hyp_mask[b * S + h] == 0) ? NEG_MASK : 0.0f;
    const float* simb = g_sim + (size_t)b * S * S;

    // phase 1: online max/sum per column, 4 strips of 128 p
    float m = -3.0e38f, s = 0.0f;
    const int p0s = strip * 128;
    for (int p = p0s; p < p0s + 128; ++p) {
        float v = simb[p * S + h] + c;
        if (v > m) { s = s * __expf(m - v) + 1.0f; m = v; }
        else       { s += __expf(v - m); }
    }

    __shared__ float sm[4][64], ss[4][64], Mf[64], If[64], Cf[64];
    sm[strip][col] = m;
    ss[strip][col] = s;
    if (strip == 0) Cf[col] = c;
    __syncthreads();
    if (strip == 0) {
        float M = -3.0e38f;
#pragma unroll
        for (int i = 0; i < 4; i++) M = fmaxf(M, sm[i][col]);
        float Ssum = 0.0f;
#pragma unroll
        for (int i = 0; i < 4; i++) Ssum += ss[i][col] * __expf(sm[i][col] - M);
        Mf[col] = M;
        If[col] = 1.0f / Ssum;
    }
    __syncthreads();

    // phase 2: compute w, transpose through smem, write [h][p] coalesced
    __shared__ __half thi[64][66], tlo[64][66];
    const float cc = Cf[col], MM = Mf[col], ii = If[col];
    for (int p0 = 0; p0 < S; p0 += 64) {
#pragma unroll
        for (int j = 0; j < 16; j++) {
            int pi = strip * 16 + j;
            float v = simb[(p0 + pi) * S + h] + cc;
            float w = __expf(v - MM) * ii;
            __half hh = __float2half_rn(w);
            thi[col][pi] = hh;
            tlo[col][pi] = __float2half_rn(w - __half2float(hh));
        }
        __syncthreads();
#pragma unroll
        for (int j = 0; j < 16; j++) {
            int hy = strip * 16 + j;
            size_t o = (size_t)b * S * S + (size_t)(h0 + hy) * S + p0 + col;
            bhi[o] = thi[hy][col];
            blo[o] = tlo[hy][col];
        }
        __syncthreads();
    }
}

// ---------------------------------------------------------------------------
extern "C" void kernel_launch(void* const* d_in, const int* in_sizes, int n_in,
                              void* d_out, int out_size)
{
    const float* premise  = (const float*)d_in[0];
    const int*   pre_mask = (const int*)  d_in[1];
    const float* hypo     = (const float*)d_in[2];
    const int*   hyp_mask = (const int*)  d_in[3];
    float* out1 = (float*)d_out;
    float* out2 = out1 + TENS;

    float*  sim;
    __half* buf;
    cudaGetSymbolAddress((void**)&sim, g_sim);
    cudaGetSymbolAddress((void**)&buf, g_buf);
    auto slot = [&](int i) { return buf + (size_t)i * TENS; };

    const int SMEM3 = 3 * 4 * 8192;   // 96 KB
    const int SMEM2 = 3 * 3 * 8192;   // 72 KB
    cudaFuncSetAttribute(gemm_tc_kernel<3>,
                         cudaFuncAttributeMaxDynamicSharedMemorySize, SMEM3);
    cudaFuncSetAttribute(gemm_tc_kernel<2>,
                         cudaFuncAttributeMaxDynamicSharedMemorySize, SMEM2);

    dim3 cgrid(16, 16, NB), cblk(32, 8);
    dim3 ggrid(4, 4, NB);

    // 1. hi/lo fp16 splits (+hi transposes)
    convert_split_kernel<<<cgrid, cblk>>>(premise, slot(PRE_HI), slot(PRE_LO), slot(PRE_THI));
    convert_split_kernel<<<cgrid, cblk>>>(hypo,    slot(HYP_HI), slot(HYP_LO), slot(HYP_THI));

    // 2. sim = premise @ hypothesis^T  (3-term split)
    gemm_tc_kernel<3><<<ggrid, 256, SMEM3>>>(slot(PRE_HI), slot(PRE_LO),
                                             slot(HYP_HI), slot(HYP_LO), sim);

    // 3. softmaxes -> fp16 hi/lo attention (attB transposed)
    softmax_row_kernel<<<dim3(S / 8, NB), 256>>>(pre_mask, slot(ATT_AHI), slot(ATT_ALO));
    softmax_col_kernel<<<dim3(S / 64, NB), 256>>>(hyp_mask, slot(ATT_BHI), slot(ATT_BLO));

    // 4. attended_premises = attA @ hyp   (2-term: att split x value-hi)
    gemm_tc_kernel<2><<<ggrid, 256, SMEM2>>>(slot(ATT_AHI), slot(ATT_ALO),
                                             slot(HYP_THI), slot(HYP_THI), out1);

    // 5. attended_hypothesis = attB^T @ pre (2-term)
    gemm_tc_kernel<2><<<ggrid, 256, SMEM2>>>(slot(ATT_BHI), slot(ATT_BLO),
                                             slot(PRE_THI), slot(PRE_THI), out2);
}

// round 5
// speedup vs baseline: 4.1620x; 1.3428x over previous
#include <cuda_runtime.h>
#include <cuda_fp16.h>
#include <cstdint>

#define NB 64
#define S  512
#define NEG_MASK -999999.0f

#define TENS ((size_t)NB * S * S)

// ---------------- scratch ---------------------------------------------------
__device__ float  g_sim[TENS];
__device__ __half g_buf[8 * TENS];

#define PRE_HI  0
#define PRE_LO  1
#define PRE_THI 2
#define HYP_HI  3
#define HYP_LO  4
#define HYP_THI 5
#define ATT_AHI 6
#define ATT_BHI 7

// ---------------- helpers ---------------------------------------------------
__device__ __forceinline__ uint32_t smem_to_u32(const void* p) {
    uint32_t a;
    asm("{ .reg .u64 t; cvta.to.shared.u64 t, %1; cvt.u32.u64 %0, t; }" : "=r"(a) : "l"(p));
    return a;
}
__device__ __forceinline__ void ldsm_x4(uint32_t* r, uint32_t addr) {
    asm volatile("ldmatrix.sync.aligned.m8n8.x4.shared.b16 {%0,%1,%2,%3}, [%4];"
                 : "=r"(r[0]), "=r"(r[1]), "=r"(r[2]), "=r"(r[3]) : "r"(addr));
}
__device__ __forceinline__ void ldsm_x2(uint32_t* r, uint32_t addr) {
    asm volatile("ldmatrix.sync.aligned.m8n8.x2.shared.b16 {%0,%1}, [%2];"
                 : "=r"(r[0]), "=r"(r[1]) : "r"(addr));
}
__device__ __forceinline__ void mma16816(float* c, const uint32_t* a, const uint32_t* b) {
    asm volatile(
        "mma.sync.aligned.m16n8k16.row.col.f32.f16.f16.f32 "
        "{%0,%1,%2,%3}, {%4,%5,%6,%7}, {%8,%9}, {%0,%1,%2,%3};"
        : "+f"(c[0]), "+f"(c[1]), "+f"(c[2]), "+f"(c[3])
        : "r"(a[0]), "r"(a[1]), "r"(a[2]), "r"(a[3]), "r"(b[0]), "r"(b[1]));
}

// ---------------------------------------------------------------------------
// Conversion: fp32 X -> hi/lo fp16 row-major + hi fp16 transposed
// grid (16,16,NB), block (32,8)
// ---------------------------------------------------------------------------
__global__ __launch_bounds__(256)
void convert_split_kernel(const float* __restrict__ X,
                          __half* __restrict__ hi, __half* __restrict__ lo,
                          __half* __restrict__ thi)
{
    __shared__ __half sh[32][33];
    const int tx = threadIdx.x, ty = threadIdx.y;
    const size_t base = (size_t)blockIdx.z * S * S;
    const int r0 = blockIdx.y * 32, c0 = blockIdx.x * 32;
#pragma unroll
    for (int j = 0; j < 4; j++) {
        int rl = ty + j * 8;
        size_t idx = base + (size_t)(r0 + rl) * S + c0 + tx;
        float x = X[idx];
        __half h = __float2half_rn(x);
        hi[idx] = h;
        lo[idx] = __float2half_rn(x - __half2float(h));
        sh[rl][tx] = h;
    }
    __syncthreads();
#pragma unroll
    for (int j = 0; j < 4; j++) {
        int cl = ty + j * 8;
        thi[base + (size_t)(c0 + cl) * S + r0 + tx] = sh[tx][cl];
    }
}

// ---------------------------------------------------------------------------
// fp16 tensor-core GEMM (mma.sync m16n8k16), K-major A and B, fp32 out.
// NTERMS=3: C = Ahi*Bhi + Ahi*Blo + Alo*Bhi   (sim GEMM, 22-bit effective)
// NTERMS=1: C = A*B                           (attended GEMMs, plain fp16)
// 128x128 CTA tile, BK=32, 3-stage cp.async, 2 CTAs/SM.
// Stage tiles (8KB each, 128 rows x 32 halves, 64B rows, chunk-XOR swizzle).
// ---------------------------------------------------------------------------
template<int NTERMS>
__global__ __launch_bounds__(256, 2)
void gemm_tc_kernel(const __half* __restrict__ Ahi, const __half* __restrict__ Alo,
                    const __half* __restrict__ Bhi, const __half* __restrict__ Blo,
                    float* __restrict__ C)
{
    constexpr int NTILES = (NTERMS == 3) ? 4 : 2;
    constexpr int TSZ    = 8192;
    constexpr int STSZ   = NTILES * TSZ;
    // tile order: NTERMS=3: Ahi | Alo | Bhi | Blo ; NTERMS=1: A | B
    constexpr int BOFFS  = (NTERMS == 3) ? 2 * TSZ : TSZ;

    extern __shared__ char smem[];
    const uint32_t sb = smem_to_u32(smem);
    const int tid = threadIdx.x;
    const int lane = tid & 31, wid = tid >> 5;
    const int wm = wid >> 2;            // 0..1
    const int wn = wid & 3;             // 0..3
    const size_t boff = (size_t)blockIdx.z * S * S;
    const int m0 = blockIdx.y * 128, n0 = blockIdx.x * 128;

    const __half* gsrc[NTILES == 4 ? 4 : 2];
    if (NTERMS == 3) {
        gsrc[0] = Ahi + boff + (size_t)m0 * S;
        gsrc[1] = Alo + boff + (size_t)m0 * S;
        gsrc[2] = Bhi + boff + (size_t)n0 * S;
        gsrc[3] = Blo + boff + (size_t)n0 * S;
    } else {
        gsrc[0] = Ahi + boff + (size_t)m0 * S;
        gsrc[1] = Bhi + boff + (size_t)n0 * S;
    }

    auto load_stage = [&](int st, int k0) {
        uint32_t base = sb + st * STSZ;
#pragma unroll
        for (int t = 0; t < NTILES; t++) {
            const __half* g = gsrc[t] + k0;
            uint32_t tb = base + t * TSZ;
#pragma unroll
            for (int j = 0; j < 2; j++) {
                int idx = j * 256 + tid;                 // 0..511 16B chunks
                int row = idx >> 2, c = idx & 3;
                uint32_t dst = tb + row * 64 + ((uint32_t)(c ^ ((row >> 1) & 3)) << 4);
                const void* src = g + row * S + c * 8;
                asm volatile("cp.async.cg.shared.global [%0], [%1], 16;"
                             :: "r"(dst), "l"(src) : "memory");
            }
        }
        asm volatile("cp.async.commit_group;" ::: "memory");
    };

    float acc[4][4][4];
#pragma unroll
    for (int i = 0; i < 4; i++)
#pragma unroll
        for (int j = 0; j < 4; j++)
#pragma unroll
            for (int q = 0; q < 4; q++) acc[i][j][q] = 0.0f;

    load_stage(0, 0);
    load_stage(1, 32);

    for (int i = 0; i < 16; i++) {
        __syncthreads();                       // prev-iter reads of stage (i+2)%3 done
        if (i + 2 < 16) load_stage((i + 2) % 3, (i + 2) * 32);
        else asm volatile("cp.async.commit_group;" ::: "memory");
        asm volatile("cp.async.wait_group 2;" ::: "memory");   // stage i landed
        __syncthreads();

        const uint32_t stb = sb + (i % 3) * STSZ;
#pragma unroll
        for (int ks = 0; ks < 2; ks++) {
            uint32_t ah[4][4], al[4][4];
#pragma unroll
            for (int mf = 0; mf < 4; mf++) {
                int row = wm * 64 + mf * 16 + (lane & 15);
                int ch = (ks * 2 + (lane >> 4)) ^ ((row >> 1) & 3);
                uint32_t off = row * 64 + (ch << 4);
                ldsm_x4(ah[mf], stb + off);
                if (NTERMS == 3) ldsm_x4(al[mf], stb + TSZ + off);
            }
#pragma unroll
            for (int nf = 0; nf < 4; nf++) {
                int row = wn * 32 + nf * 8 + (lane & 7);
                int ch = (ks * 2 + ((lane >> 3) & 1)) ^ ((row >> 1) & 3);
                uint32_t off = row * 64 + (ch << 4);
                uint32_t bh[2], bl[2];
                ldsm_x2(bh, stb + BOFFS + off);
                if (NTERMS == 3) ldsm_x2(bl, stb + BOFFS + TSZ + off);
#pragma unroll
                for (int mf = 0; mf < 4; mf++) {
                    mma16816(acc[mf][nf], ah[mf], bh);
                    if (NTERMS == 3) {
                        mma16816(acc[mf][nf], ah[mf], bl);
                        mma16816(acc[mf][nf], al[mf], bh);
                    }
                }
            }
        }
    }

    float* Cb = C + boff;
#pragma unroll
    for (int mf = 0; mf < 4; mf++) {
#pragma unroll
        for (int nf = 0; nf < 4; nf++) {
            int r  = m0 + wm * 64 + mf * 16 + (lane >> 2);
            int cc = n0 + wn * 32 + nf * 8 + (lane & 3) * 2;
            *(float2*)&Cb[(size_t)r * S + cc]       = make_float2(acc[mf][nf][0], acc[mf][nf][1]);
            *(float2*)&Cb[(size_t)(r + 8) * S + cc] = make_float2(acc[mf][nf][2], acc[mf][nf][3]);
        }
    }
}

// ---------------------------------------------------------------------------
// Row softmax (attention_a): one warp per row, shfl reductions -> fp16 hi only.
// grid (S/8, NB), block 256
// ---------------------------------------------------------------------------
__global__ __launch_bounds__(256)
void softmax_row_kernel(const int* __restrict__ pre_mask,
                        __half* __restrict__ ahi)
{
    const int b = blockIdx.y;
    const int w = threadIdx.x >> 5, lane = threadIdx.x & 31;
    const int p = blockIdx.x * 8 + w;
    const float c = (pre_mask[b * S + p] == 0) ? NEG_MASK : 0.0f;
    const size_t off = ((size_t)b * S + p) * S;
    const float* row = g_sim + off;

    float4 v[4];
#pragma unroll
    for (int seg = 0; seg < 4; seg++) {
        v[seg] = *(const float4*)&row[seg * 128 + lane * 4];
        v[seg].x += c; v[seg].y += c; v[seg].z += c; v[seg].w += c;
    }

    float M = -3.0e38f;
#pragma unroll
    for (int seg = 0; seg < 4; seg++)
        M = fmaxf(M, fmaxf(fmaxf(v[seg].x, v[seg].y), fmaxf(v[seg].z, v[seg].w)));
#pragma unroll
    for (int o = 16; o > 0; o >>= 1)
        M = fmaxf(M, __shfl_xor_sync(0xFFFFFFFFu, M, o));

    float s = 0.0f;
    float4 e[4];
#pragma unroll
    for (int seg = 0; seg < 4; seg++) {
        e[seg].x = __expf(v[seg].x - M); e[seg].y = __expf(v[seg].y - M);
        e[seg].z = __expf(v[seg].z - M); e[seg].w = __expf(v[seg].w - M);
        s += e[seg].x + e[seg].y + e[seg].z + e[seg].w;
    }
#pragma unroll
    for (int o = 16; o > 0; o >>= 1)
        s += __shfl_xor_sync(0xFFFFFFFFu, s, o);
    const float inv = 1.0f / s;

#pragma unroll
    for (int seg = 0; seg < 4; seg++) {
        size_t o4 = off + seg * 128 + lane * 4;
        *(__half2*)&ahi[o4]     = __halves2half2(__float2half_rn(e[seg].x * inv),
                                                 __float2half_rn(e[seg].y * inv));
        *(__half2*)&ahi[o4 + 2] = __halves2half2(__float2half_rn(e[seg].z * inv),
                                                 __float2half_rn(e[seg].w * inv));
    }
}

// ---------------------------------------------------------------------------
// Column softmax (attention_b) -> fp16 hi written TRANSPOSED [h][p],
// coalesced via 64x64 smem transpose tiles. grid (S/64, NB), block 256.
// ---------------------------------------------------------------------------
__global__ __launch_bounds__(256)
void softmax_col_kernel(const int* __restrict__ hyp_mask,
                        __half* __restrict__ bhi)
{
    const int b   = blockIdx.y;
    const int h0  = blockIdx.x * 64;
    const int t   = threadIdx.x;
    const int col = t & 63, strip = t >> 6;
    const int h   = h0 + col;
    const float c = (hyp_mask[b * S + h] == 0) ? NEG_MASK : 0.0f;
    const float* simb = g_sim + (size_t)b * S * S;

    // phase 1: online max/sum per column, 4 strips of 128 p
    float m = -3.0e38f, s = 0.0f;
    const int p0s = strip * 128;
    for (int p = p0s; p < p0s + 128; ++p) {
        float v = simb[p * S + h] + c;
        if (v > m) { s = s * __expf(m - v) + 1.0f; m = v; }
        else       { s += __expf(v - m); }
    }

    __shared__ float sm[4][64], ss[4][64], Mf[64], If[64], Cf[64];
    sm[strip][col] = m;
    ss[strip][col] = s;
    if (strip == 0) Cf[col] = c;
    __syncthreads();
    if (strip == 0) {
        float M = -3.0e38f;
#pragma unroll
        for (int i = 0; i < 4; i++) M = fmaxf(M, sm[i][col]);
        float Ssum = 0.0f;
#pragma unroll
        for (int i = 0; i < 4; i++) Ssum += ss[i][col] * __expf(sm[i][col] - M);
        Mf[col] = M;
        If[col] = 1.0f / Ssum;
    }
    __syncthreads();

    // phase 2: compute w, transpose through smem, write [h][p] coalesced
    __shared__ __half thi[64][66];
    const float cc = Cf[col], MM = Mf[col], ii = If[col];
    for (int p0 = 0; p0 < S; p0 += 64) {
#pragma unroll
        for (int j = 0; j < 16; j++) {
            int pi = strip * 16 + j;
            float v = simb[(p0 + pi) * S + h] + cc;
            thi[col][pi] = __float2half_rn(__expf(v - MM) * ii);
        }
        __syncthreads();
#pragma unroll
        for (int j = 0; j < 16; j++) {
            int hy = strip * 16 + j;
            size_t o = (size_t)b * S * S + (size_t)(h0 + hy) * S + p0 + col;
            bhi[o] = thi[hy][col];
        }
        __syncthreads();
    }
}

// ---------------------------------------------------------------------------
extern "C" void kernel_launch(void* const* d_in, const int* in_sizes, int n_in,
                              void* d_out, int out_size)
{
    const float* premise  = (const float*)d_in[0];
    const int*   pre_mask = (const int*)  d_in[1];
    const float* hypo     = (const float*)d_in[2];
    const int*   hyp_mask = (const int*)  d_in[3];
    float* out1 = (float*)d_out;
    float* out2 = out1 + TENS;

    float*  sim;
    __half* buf;
    cudaGetSymbolAddress((void**)&sim, g_sim);
    cudaGetSymbolAddress((void**)&buf, g_buf);
    auto slot = [&](int i) { return buf + (size_t)i * TENS; };

    const int SMEM3 = 3 * 4 * 8192;   // 96 KB
    const int SMEM1 = 3 * 2 * 8192;   // 48 KB
    cudaFuncSetAttribute(gemm_tc_kernel<3>,
                         cudaFuncAttributeMaxDynamicSharedMemorySize, SMEM3);
    cudaFuncSetAttribute(gemm_tc_kernel<1>,
                         cudaFuncAttributeMaxDynamicSharedMemorySize, SMEM1);

    dim3 cgrid(16, 16, NB), cblk(32, 8);
    dim3 ggrid(4, 4, NB);

    // 1. hi/lo fp16 splits (+hi transposes)
    convert_split_kernel<<<cgrid, cblk>>>(premise, slot(PRE_HI), slot(PRE_LO), slot(PRE_THI));
    convert_split_kernel<<<cgrid, cblk>>>(hypo,    slot(HYP_HI), slot(HYP_LO), slot(HYP_THI));

    // 2. sim = premise @ hypothesis^T  (3-term split, 22-bit effective)
    gemm_tc_kernel<3><<<ggrid, 256, SMEM3>>>(slot(PRE_HI), slot(PRE_LO),
                                             slot(HYP_HI), slot(HYP_LO), sim);

    // 3. softmaxes -> fp16 attention (attB transposed)
    softmax_row_kernel<<<dim3(S / 8, NB), 256>>>(pre_mask, slot(ATT_AHI));
    softmax_col_kernel<<<dim3(S / 64, NB), 256>>>(hyp_mask, slot(ATT_BHI));

    // 4. attended_premises = attA @ hyp    (plain fp16)
    gemm_tc_kernel<1><<<ggrid, 256, SMEM1>>>(slot(ATT_AHI), nullptr,
                                             slot(HYP_THI), nullptr, out1);

    // 5. attended_hypothesis = attB^T @ pre (plain fp16)
    gemm_tc_kernel<1><<<ggrid, 256, SMEM1>>>(slot(ATT_BHI), nullptr,
                                             slot(PRE_THI), nullptr, out2);
}